// round 2
// baseline (speedup 1.0000x reference)
#include <cuda_runtime.h>
#include <math.h>
#include <stdint.h>

#define BATCH 256
#define VOCAB 128000
#define NBINS 8192
#define CAP   4096
#define NEG_INF __int_as_float(0xff800000)

// ---------------- scratch (device globals; no allocations allowed) ----------
__device__ float  g_Ms[BATCH];        // max of scaled logits
__device__ int    g_greedy[BATCH];    // argmax of raw logits, first occurrence
__device__ double g_Z[BATCH];         // sum exp(scaled - Ms)
__device__ int    g_Bstar[BATCH];     // boundary bin
__device__ double g_cumAbove[BATCH];  // exp-mass strictly above boundary bin
__device__ unsigned long long g_cut[BATCH]; // keep(v) <=> pack(v) >= g_cut

// monotone float->uint key (matches total order for non-NaN, -0 < +0)
__device__ __forceinline__ unsigned okey(float f){
    unsigned b = __float_as_uint(f);
    return b ^ ((b & 0x80000000u) ? 0xFFFFFFFFu : 0x80000000u);
}

// jax threefry2x32-20, key = (0, 42) from jax.random.key(42)
__device__ __forceinline__ void threefry(unsigned c0, unsigned c1,
                                         unsigned &o0, unsigned &o1){
    const unsigned k0 = 0u, k1 = 42u;
    const unsigned k2 = 0x1BD11BDAu ^ k0 ^ k1;
    unsigned x0 = c0 + k0, x1 = c1 + k1;
#define TFR(r) { x0 += x1; x1 = ((x1 << r) | (x1 >> (32 - r))); x1 ^= x0; }
    TFR(13) TFR(15) TFR(26) TFR(6)   x0 += k1; x1 += k2 + 1u;
    TFR(17) TFR(29) TFR(16) TFR(24)  x0 += k2; x1 += k0 + 2u;
    TFR(13) TFR(15) TFR(26) TFR(6)   x0 += k0; x1 += k1 + 3u;
    TFR(17) TFR(29) TFR(16) TFR(24)  x0 += k1; x1 += k2 + 4u;
    TFR(13) TFR(15) TFR(26) TFR(6)   x0 += k2; x1 += k0 + 5u;
#undef TFR
    o0 = x0; o1 = x1;
}

// jax threefry_partitionable 32-bit bits for flat element index i (< 2^32):
// counter = (hi=0, lo=i), bits = o0 ^ o1
__device__ __forceinline__ unsigned jax_bits32(unsigned i){
    unsigned o0, o1;
    threefry(0u, i, o0, o1);
    return o0 ^ o1;
}

// jax: u = bitcast((bits>>9)|0x3f800000)-1; u'=max(u,tiny); g=-log(-log(u'))
__device__ __forceinline__ float gumbel_from_bits(unsigned bits){
    float u = __uint_as_float((bits >> 9) | 0x3f800000u) - 1.0f;
    if (u <= 0.0f) u = 1.17549435e-38f;
    float inner = -log1pf(u - 1.0f);   // == -log(u) exactly, fast-math-immune
    return -logf(inner);
}

// ---------------- K1: row max (greedy = first occurrence) -------------------
__global__ void k1_max(const float* __restrict__ logits,
                       const float* __restrict__ temps){
    int row = blockIdx.x;
    const float* x = logits + (size_t)row * VOCAB;
    float bv = NEG_INF; int bi = 0;
    for (int v = threadIdx.x; v < VOCAB; v += blockDim.x){
        float val = x[v];
        if (val > bv){ bv = val; bi = v; }   // strict > keeps smallest index
    }
    __shared__ float sv[1024]; __shared__ int si[1024];
    sv[threadIdx.x] = bv; si[threadIdx.x] = bi; __syncthreads();
    for (int s = blockDim.x >> 1; s > 0; s >>= 1){
        if (threadIdx.x < s){
            float ov = sv[threadIdx.x + s]; int oi = si[threadIdx.x + s];
            if (ov > sv[threadIdx.x] ||
                (ov == sv[threadIdx.x] && oi < si[threadIdx.x])){
                sv[threadIdx.x] = ov; si[threadIdx.x] = oi;
            }
        }
        __syncthreads();
    }
    if (threadIdx.x == 0){
        float t = temps[row]; float ts = (t == 0.0f) ? 1.0f : t;
        g_greedy[row] = si[0];
        g_Ms[row] = __fdiv_rn(sv[0], ts);
    }
}

// ---------------- K2: Z + value histogram + boundary bin --------------------
__global__ void k2_hist(const float* __restrict__ logits,
                        const float* __restrict__ temps,
                        const float* __restrict__ topps){
    int row = blockIdx.x;
    __shared__ float  bins[NBINS];
    __shared__ double sarr[1024];
    __shared__ int    sbi[1024];
    __shared__ double sZ;
    for (int i = threadIdx.x; i < NBINS; i += blockDim.x) bins[i] = 0.0f;
    __syncthreads();

    float t = temps[row]; float ts = (t == 0.0f) ? 1.0f : t;
    float Ms = g_Ms[row];
    const float* x = logits + (size_t)row * VOCAB;
    double zloc = 0.0;
    for (int v = threadIdx.x; v < VOCAB; v += blockDim.x){
        float s = __fdiv_rn(x[v], ts);
        float e = expf(s - Ms);
        atomicAdd(&bins[okey(s) >> 19], e);
        zloc += e;
    }
    sarr[threadIdx.x] = zloc; __syncthreads();
    for (int s2 = 512; s2 > 0; s2 >>= 1){
        if (threadIdx.x < s2) sarr[threadIdx.x] += sarr[threadIdx.x + s2];
        __syncthreads();
    }
    if (threadIdx.x == 0) sZ = sarr[0];
    __syncthreads();
    double Z = sZ;

    // chunk sums: 8 bins / thread, then inclusive SUFFIX scan (Hillis-Steele)
    int base = threadIdx.x * 8;
    double csum = 0.0;
#pragma unroll
    for (int j = 0; j < 8; j++) csum += (double)bins[base + j];
    __syncthreads();
    sarr[threadIdx.x] = csum; __syncthreads();
    for (int off = 1; off < 1024; off <<= 1){
        double v = sarr[threadIdx.x];
        double a = (threadIdx.x + off < 1024) ? sarr[threadIdx.x + off] : 0.0;
        __syncthreads();
        sarr[threadIdx.x] = v + a;
        __syncthreads();
    }
    double above = sarr[threadIdx.x] - csum;   // mass in chunks strictly above

    float p = fminf(fmaxf(topps[row], 0.0f), 1.0f);
    double pZ = (double)p * Z;

    // walk own chunk high->low: highest bin whose inclusive-suffix > pZ
    int bestj = -1; double bestAbove = 0.0;
    double run = above;
    for (int j = 7; j >= 0; j--){
        int bin = base + j;
        double s = (double)bins[bin];
        if (run + s > pZ){ bestj = bin; bestAbove = run; break; }
        run += s;
    }
    __syncthreads();
    sbi[threadIdx.x] = bestj; sarr[threadIdx.x] = bestAbove; __syncthreads();
    for (int s2 = 512; s2 > 0; s2 >>= 1){
        if (threadIdx.x < s2 && sbi[threadIdx.x + s2] > sbi[threadIdx.x]){
            sbi[threadIdx.x] = sbi[threadIdx.x + s2];
            sarr[threadIdx.x] = sarr[threadIdx.x + s2];
        }
        __syncthreads();
    }
    if (threadIdx.x == 0){
        g_Bstar[row] = sbi[0];
        g_cumAbove[row] = sarr[0];
        g_Z[row] = Z;
    }
}

// ---------------- K3: resolve exact cutoff inside boundary bin --------------
__global__ void k3_cut(const float* __restrict__ logits,
                       const float* __restrict__ temps,
                       const float* __restrict__ topps){
    int row = blockIdx.x;
    __shared__ unsigned long long keys[CAP];
    __shared__ double sarr[1024];
    __shared__ int sli[1024];
    __shared__ int scnt;
    int Bstar = g_Bstar[row];
    if (Bstar < 0){ if (threadIdx.x == 0) g_cut[row] = 0ULL; return; }
    if (threadIdx.x == 0) scnt = 0;
    __syncthreads();

    float t = temps[row]; float ts = (t == 0.0f) ? 1.0f : t;
    float Ms = g_Ms[row];
    const float* x = logits + (size_t)row * VOCAB;
    for (int v = threadIdx.x; v < VOCAB; v += blockDim.x){
        float s = __fdiv_rn(x[v], ts);
        unsigned k = okey(s);
        if ((int)(k >> 19) == Bstar){
            int pos = atomicAdd(&scnt, 1);
            if (pos < CAP)
                keys[pos] = ((unsigned long long)k << 32) | (unsigned)v;
        }
    }
    __syncthreads();
    int count = min(scnt, CAP);
    if (count == 0){
        if (threadIdx.x == 0)
            g_cut[row] = ((unsigned long long)(unsigned)Bstar) << (19 + 32);
        return;
    }
    int n = 1; while (n < count) n <<= 1; if (n < 2) n = 2;
    for (int i = count + threadIdx.x; i < n; i += blockDim.x) keys[i] = 0ULL;
    __syncthreads();

    // bitonic sort DESCENDING on packed (okey, idx)
    for (int k2 = 2; k2 <= n; k2 <<= 1){
        for (int j = k2 >> 1; j > 0; j >>= 1){
            for (int i = threadIdx.x; i < n; i += blockDim.x){
                int ixj = i ^ j;
                if (ixj > i){
                    unsigned long long a = keys[i], b = keys[ixj];
                    bool seg = ((i & k2) == 0);
                    if (seg ? (a < b) : (a > b)){ keys[i] = b; keys[ixj] = a; }
                }
            }
            __syncthreads();
        }
    }

    // forward prefix of exp over sorted order; last kept index
    double pZ = (double)fminf(fmaxf(topps[row], 0.0f), 1.0f) * g_Z[row];
    double cumAbove = g_cumAbove[row];
    int m = (n + blockDim.x - 1) / blockDim.x;   // <= 4
    int lo = threadIdx.x * m;
    float ev[4];
    double ls = 0.0;
    for (int q = 0; q < m; q++){
        int i = lo + q; float e = 0.0f;
        if (i < count){
            int idx = (int)(keys[i] & 0xFFFFFFFFu);
            float s = __fdiv_rn(x[idx], ts);
            e = expf(s - Ms);
        }
        ev[q] = e; ls += e;
    }
    sarr[threadIdx.x] = ls; __syncthreads();
    for (int off = 1; off < 1024; off <<= 1){
        double v = sarr[threadIdx.x];
        double a = (threadIdx.x >= off) ? sarr[threadIdx.x - off] : 0.0;
        __syncthreads();
        sarr[threadIdx.x] = v + a;
        __syncthreads();
    }
    double run = sarr[threadIdx.x] - ls + cumAbove;
    int lastKept = -1;
    for (int q = 0; q < m; q++){
        int i = lo + q;
        run += (double)ev[q];
        if (i < count && run <= pZ) lastKept = i;
    }
    sli[threadIdx.x] = lastKept; __syncthreads();
    for (int s2 = 512; s2 > 0; s2 >>= 1){
        if (threadIdx.x < s2)
            sli[threadIdx.x] = max(sli[threadIdx.x], sli[threadIdx.x + s2]);
        __syncthreads();
    }
    if (threadIdx.x == 0){
        int iL = sli[0];
        unsigned long long C;
        if (iL >= 0)              C = keys[iL];
        else if (cumAbove > 0.0)  C = ((unsigned long long)(unsigned)(Bstar + 1)) << (19 + 32);
        else                      C = keys[0];   // force-keep sorted-pos-0
        g_cut[row] = C;
    }
}

// ---------------- K4: gumbel-max sampling (partitionable threefry) ----------
__global__ void k4_sample(const float* __restrict__ logits,
                          const float* __restrict__ temps,
                          float* __restrict__ out){
    int row = blockIdx.x;
    const float* x = logits + (size_t)row * VOCAB;
    float t = temps[row];
    float ts = (t == 0.0f) ? 1.0f : t;
    float Ms = g_Ms[row];
    unsigned long long C = g_cut[row];
    unsigned iBase = (unsigned)row * (unsigned)VOCAB;

    float bs = NEG_INF; int bi = -1;
    double sk = 0.0;

    for (int v = threadIdx.x; v < VOCAB; v += blockDim.x){
        float s = __fdiv_rn(x[v], ts);
        unsigned long long pk =
            ((unsigned long long)okey(s) << 32) | (unsigned)v;
        if (pk >= C){
            sk += (double)expf(s - Ms);
            unsigned bits = jax_bits32(iBase + (unsigned)v);
            float sc = s + gumbel_from_bits(bits);
            if (sc > bs || (sc == bs && (unsigned)v < (unsigned)bi)){
                bs = sc; bi = v;
            }
        }
    }

    __shared__ float  fv[1024];
    __shared__ int    iv[1024];
    __shared__ double dv[1024];

    fv[threadIdx.x] = bs; iv[threadIdx.x] = bi; dv[threadIdx.x] = sk;
    __syncthreads();
    for (int s = blockDim.x >> 1; s > 0; s >>= 1){
        if (threadIdx.x < s){
            float ov = fv[threadIdx.x + s]; int oi = iv[threadIdx.x + s];
            if (ov > fv[threadIdx.x] ||
                (ov == fv[threadIdx.x] &&
                 (unsigned)oi < (unsigned)iv[threadIdx.x])){
                fv[threadIdx.x] = ov; iv[threadIdx.x] = oi;
            }
            dv[threadIdx.x] += dv[threadIdx.x + s];
        }
        __syncthreads();
    }

    if (threadIdx.x == 0){
        int tok = (t == 0.0f) ? g_greedy[row] : iv[0];
        if (tok < 0) tok = g_greedy[row];   // safety (kept set never empty)
        float stok = __fdiv_rn(x[tok], ts);
        unsigned long long pT =
            ((unsigned long long)okey(stok) << 32) | (unsigned)tok;
        float sel = (pT >= C) ? stok : NEG_INF;
        double lz = (double)Ms + log(dv[0]);
        out[row]          = (float)tok;
        out[BATCH + row]  = (float)((double)sel - lz);
    }
}

// ---------------- launch ----------------------------------------------------
extern "C" void kernel_launch(void* const* d_in, const int* in_sizes, int n_in,
                              void* d_out, int out_size){
    const float* logits = (const float*)d_in[0];
    const float* temps  = (const float*)d_in[1];
    const float* topps  = (const float*)d_in[2];
    float* out = (float*)d_out;

    k1_max   <<<BATCH, 1024>>>(logits, temps);
    k2_hist  <<<BATCH, 1024>>>(logits, temps, topps);
    k3_cut   <<<BATCH, 1024>>>(logits, temps, topps);
    k4_sample<<<BATCH, 1024>>>(logits, temps, out);
}

// round 3
// speedup vs baseline: 1.2049x; 1.2049x over previous
#include <cuda_runtime.h>
#include <math.h>
#include <stdint.h>

#define BATCH 256
#define VOCAB 128000
#define V4    (VOCAB/4)     // 32000
#define NBINS 8192
#define CAP   4096
#define NEG_INF __int_as_float(0xff800000)

// ---------------- scratch (device globals; no allocations allowed) ----------
__device__ unsigned long long g_rowmax[BATCH]; // (okey(x)<<32) | ~argmax
__device__ double g_Z[BATCH];
__device__ int    g_Bstar[BATCH];
__device__ double g_cumAbove[BATCH];
__device__ unsigned long long g_cut[BATCH];    // keep <=> (okey(s),v) >= cut

// monotone float->uint key (total order, -0 < +0)
__device__ __forceinline__ unsigned okey(float f){
    unsigned b = __float_as_uint(f);
    return b ^ ((b & 0x80000000u) ? 0xFFFFFFFFu : 0x80000000u);
}
__device__ __forceinline__ float key_to_float(unsigned k){
    unsigned b = (k & 0x80000000u) ? (k ^ 0x80000000u) : ~k;
    return __uint_as_float(b);
}

// jax threefry2x32-20, key = (0, 42)
__device__ __forceinline__ void threefry(unsigned c0, unsigned c1,
                                         unsigned &o0, unsigned &o1){
    const unsigned k0 = 0u, k1 = 42u;
    const unsigned k2 = 0x1BD11BDAu ^ k0 ^ k1;
    unsigned x0 = c0 + k0, x1 = c1 + k1;
#define TFR(r) { x0 += x1; x1 = ((x1 << r) | (x1 >> (32 - r))); x1 ^= x0; }
    TFR(13) TFR(15) TFR(26) TFR(6)   x0 += k1; x1 += k2 + 1u;
    TFR(17) TFR(29) TFR(16) TFR(24)  x0 += k2; x1 += k0 + 2u;
    TFR(13) TFR(15) TFR(26) TFR(6)   x0 += k0; x1 += k1 + 3u;
    TFR(17) TFR(29) TFR(16) TFR(24)  x0 += k1; x1 += k2 + 4u;
    TFR(13) TFR(15) TFR(26) TFR(6)   x0 += k2; x1 += k0 + 5u;
#undef TFR
    o0 = x0; o1 = x1;
}
// partitionable bits: counter (0, i), bits = o0 ^ o1
__device__ __forceinline__ unsigned jax_bits32(unsigned i){
    unsigned o0, o1; threefry(0u, i, o0, o1); return o0 ^ o1;
}
__device__ __forceinline__ float gumbel_from_bits(unsigned bits){
    float u = __uint_as_float((bits >> 9) | 0x3f800000u) - 1.0f;
    if (u <= 0.0f) u = 1.17549435e-38f;
    float inner = -log1pf(u - 1.0f);   // == -log(u) exactly
    return -logf(inner);
}

// minimal raw key kx in [0x00800000, 0xFF800000] with okey(rn(x/ts)) >= target
__device__ unsigned lower_bound_key(float ts, unsigned target){
    unsigned lo = 0x00800000u, hi = 0xFF800000u;
    while (lo < hi){
        unsigned mid = lo + ((hi - lo) >> 1);
        float x = key_to_float(mid);
        unsigned sk = okey(__fdiv_rn(x, ts));
        if (sk >= target) hi = mid; else lo = mid + 1;
    }
    return lo;   // 0xFF800000 sentinel if none (all finite data keys < it)
}

// ---------------- K0: init ---------------------------------------------------
__global__ void k0_init(){
    if (threadIdx.x < BATCH) g_rowmax[threadIdx.x] = 0ULL;
}

// ---------------- K1: row max (4 blocks/row, raw values, no div) -------------
__global__ void k1_max(const float* __restrict__ logits){
    int row  = blockIdx.y;
    int part = blockIdx.x;                 // 0..3
    int vbase = part * (VOCAB / 4);        // element offset in row
    const float4* x4 = (const float4*)(logits + (size_t)row * VOCAB + vbase);
    unsigned long long best = 0ULL;
    for (int i = threadIdx.x; i < (VOCAB / 16); i += blockDim.x){ // 8000 f4
        float4 f = x4[i];
        unsigned v0 = (unsigned)(vbase + 4 * i);
        float vals[4] = {f.x, f.y, f.z, f.w};
#pragma unroll
        for (int j = 0; j < 4; j++){
            unsigned long long p =
                ((unsigned long long)okey(vals[j]) << 32) | (unsigned)(~(v0 + j));
            if (p > best) best = p;
        }
    }
    __shared__ unsigned long long sp[512];
    sp[threadIdx.x] = best; __syncthreads();
    for (int s = blockDim.x >> 1; s > 0; s >>= 1){
        if (threadIdx.x < s && sp[threadIdx.x + s] > sp[threadIdx.x])
            sp[threadIdx.x] = sp[threadIdx.x + s];
        __syncthreads();
    }
    if (threadIdx.x == 0) atomicMax(&g_rowmax[row], sp[0]);
}

// ---------------- K2: Z + value histogram + boundary bin ---------------------
__global__ void k2_hist(const float* __restrict__ logits,
                        const float* __restrict__ temps,
                        const float* __restrict__ topps){
    int row = blockIdx.x;
    __shared__ float  bins[NBINS];   // 32KB
    __shared__ double sarr[1024];    // 8KB
    __shared__ int    sbi[1024];     // 4KB
    __shared__ float  sMs;
    __shared__ double sZ;
    for (int i = threadIdx.x; i < NBINS; i += blockDim.x) bins[i] = 0.0f;

    float t = temps[row]; float ts = (t == 0.0f) ? 1.0f : t;
    if (threadIdx.x == 0)
        sMs = __fdiv_rn(key_to_float((unsigned)(g_rowmax[row] >> 32)), ts);
    __syncthreads();
    float Ms = sMs;

    const float4* x4 = (const float4*)(logits + (size_t)row * VOCAB);
    float zloc = 0.0f;
    for (int i = threadIdx.x; i < V4; i += blockDim.x){
        float4 f = x4[i];
        float vals[4] = {f.x, f.y, f.z, f.w};
#pragma unroll
        for (int j = 0; j < 4; j++){
            float s = __fdiv_rn(vals[j], ts);
            float e = __expf(s - Ms);
            atomicAdd(&bins[okey(s) >> 19], e);
            zloc += e;
        }
    }
    sarr[threadIdx.x] = (double)zloc; __syncthreads();
    for (int s2 = 512; s2 > 0; s2 >>= 1){
        if (threadIdx.x < s2) sarr[threadIdx.x] += sarr[threadIdx.x + s2];
        __syncthreads();
    }
    if (threadIdx.x == 0) sZ = sarr[0];
    __syncthreads();
    double Z = sZ;

    // chunk sums (8 bins/thread) + inclusive SUFFIX scan
    int base = threadIdx.x * 8;
    double csum = 0.0;
#pragma unroll
    for (int j = 0; j < 8; j++) csum += (double)bins[base + j];
    __syncthreads();
    sarr[threadIdx.x] = csum; __syncthreads();
    for (int off = 1; off < 1024; off <<= 1){
        double v = sarr[threadIdx.x];
        double a = (threadIdx.x + off < 1024) ? sarr[threadIdx.x + off] : 0.0;
        __syncthreads();
        sarr[threadIdx.x] = v + a;
        __syncthreads();
    }
    double above = sarr[threadIdx.x] - csum;

    float p = fminf(fmaxf(topps[row], 0.0f), 1.0f);
    double pZ = (double)p * Z;

    int bestj = -1; double bestAbove = 0.0;
    double run = above;
    for (int j = 7; j >= 0; j--){
        int bin = base + j;
        double s = (double)bins[bin];
        if (run + s > pZ){ bestj = bin; bestAbove = run; break; }
        run += s;
    }
    __syncthreads();
    sbi[threadIdx.x] = bestj; sarr[threadIdx.x] = bestAbove; __syncthreads();
    for (int s2 = 512; s2 > 0; s2 >>= 1){
        if (threadIdx.x < s2 && sbi[threadIdx.x + s2] > sbi[threadIdx.x]){
            sbi[threadIdx.x] = sbi[threadIdx.x + s2];
            sarr[threadIdx.x] = sarr[threadIdx.x + s2];
        }
        __syncthreads();
    }
    if (threadIdx.x == 0){
        g_Bstar[row] = sbi[0];
        g_cumAbove[row] = sarr[0];
        g_Z[row] = Z;
    }
}

// ---------------- K3: exact cutoff in boundary bin (raw-key fast filter) -----
__global__ void k3_cut(const float* __restrict__ logits,
                       const float* __restrict__ temps,
                       const float* __restrict__ topps){
    int row = blockIdx.x;
    __shared__ unsigned long long keys[CAP];   // 32KB
    __shared__ double sarr[1024];
    __shared__ int sli[1024];
    __shared__ int scnt;
    __shared__ float sMs;
    __shared__ unsigned sKLo, sKHi;

    int Bstar = g_Bstar[row];
    if (Bstar < 0){ if (threadIdx.x == 0) g_cut[row] = 0ULL; return; }

    float t = temps[row]; float ts = (t == 0.0f) ? 1.0f : t;
    if (threadIdx.x == 0){
        scnt = 0;
        sMs = __fdiv_rn(key_to_float((unsigned)(g_rowmax[row] >> 32)), ts);
        sKLo = lower_bound_key(ts, (unsigned)Bstar << 19);
        sKHi = lower_bound_key(ts, (unsigned)(Bstar + 1) << 19);
    }
    __syncthreads();
    float Ms = sMs; unsigned kLo = sKLo, kHi = sKHi;

    const float* x = logits + (size_t)row * VOCAB;
    const float4* x4 = (const float4*)x;
    for (int i = threadIdx.x; i < V4; i += blockDim.x){
        float4 f = x4[i];
        unsigned v0 = 4u * (unsigned)i;
        float vals[4] = {f.x, f.y, f.z, f.w};
#pragma unroll
        for (int j = 0; j < 4; j++){
            unsigned kx = okey(vals[j]);
            if (kx >= kLo && kx < kHi){
                float s = __fdiv_rn(vals[j], ts);
                int pos = atomicAdd(&scnt, 1);
                if (pos < CAP)
                    keys[pos] = ((unsigned long long)okey(s) << 32) | (v0 + j);
            }
        }
    }
    __syncthreads();
    int count = min(scnt, CAP);
    if (count == 0){
        if (threadIdx.x == 0)
            g_cut[row] = ((unsigned long long)((unsigned)Bstar << 19)) << 32;
        return;
    }
    int n = 1; while (n < count) n <<= 1; if (n < 2) n = 2;
    for (int i = count + threadIdx.x; i < n; i += blockDim.x) keys[i] = 0ULL;
    __syncthreads();

    // bitonic sort DESCENDING on packed (okey(s), idx)
    for (int k2 = 2; k2 <= n; k2 <<= 1){
        for (int j = k2 >> 1; j > 0; j >>= 1){
            for (int i = threadIdx.x; i < n; i += blockDim.x){
                int ixj = i ^ j;
                if (ixj > i){
                    unsigned long long a = keys[i], b = keys[ixj];
                    bool seg = ((i & k2) == 0);
                    if (seg ? (a < b) : (a > b)){ keys[i] = b; keys[ixj] = a; }
                }
            }
            __syncthreads();
        }
    }

    // prefix of exp over sorted order; last kept index
    double pZ = (double)fminf(fmaxf(topps[row], 0.0f), 1.0f) * g_Z[row];
    double cumAbove = g_cumAbove[row];
    int m = (n + blockDim.x - 1) / blockDim.x;   // <= 4
    int lo = threadIdx.x * m;
    float ev[4];
    double ls = 0.0;
    for (int q = 0; q < m; q++){
        int i = lo + q; float e = 0.0f;
        if (i < count){
            float sv = key_to_float((unsigned)(keys[i] >> 32));
            e = __expf(sv - Ms);
        }
        ev[q] = e; ls += e;
    }
    sarr[threadIdx.x] = ls; __syncthreads();
    for (int off = 1; off < 1024; off <<= 1){
        double v = sarr[threadIdx.x];
        double a = (threadIdx.x >= off) ? sarr[threadIdx.x - off] : 0.0;
        __syncthreads();
        sarr[threadIdx.x] = v + a;
        __syncthreads();
    }
    double run = sarr[threadIdx.x] - ls + cumAbove;
    int lastKept = -1;
    for (int q = 0; q < m; q++){
        int i = lo + q;
        run += (double)ev[q];
        if (i < count && run <= pZ) lastKept = i;
    }
    sli[threadIdx.x] = lastKept; __syncthreads();
    for (int s2 = 512; s2 > 0; s2 >>= 1){
        if (threadIdx.x < s2)
            sli[threadIdx.x] = max(sli[threadIdx.x], sli[threadIdx.x + s2]);
        __syncthreads();
    }
    if (threadIdx.x == 0){
        int iL = sli[0];
        unsigned long long C;
        if (iL >= 0)              C = keys[iL];
        else if (cumAbove > 0.0)  C = ((unsigned long long)((unsigned)(Bstar + 1) << 19)) << 32;
        else                      C = keys[0];   // force-keep top of bin
        g_cut[row] = C;
    }
}

// ---------------- K4: gumbel-max sampling (raw-key fast filter) --------------
__global__ void k4_sample(const float* __restrict__ logits,
                          const float* __restrict__ temps,
                          float* __restrict__ out){
    int row = blockIdx.x;
    const float* x = logits + (size_t)row * VOCAB;
    const float4* x4 = (const float4*)x;
    float t = temps[row];
    float ts = (t == 0.0f) ? 1.0f : t;

    __shared__ float sMs;
    __shared__ unsigned sKEq, sKGt;
    unsigned long long C = g_cut[row];
    unsigned hiC = (unsigned)(C >> 32);
    unsigned loC = (unsigned)C;
    if (threadIdx.x == 0){
        sMs = __fdiv_rn(key_to_float((unsigned)(g_rowmax[row] >> 32)), ts);
        sKEq = lower_bound_key(ts, hiC);
        sKGt = (hiC == 0xFFFFFFFFu) ? 0xFF800000u
                                    : lower_bound_key(ts, hiC + 1u);
    }
    __syncthreads();
    float Ms = sMs; unsigned kEq = sKEq, kGt = sKGt;
    unsigned iBase = (unsigned)row * (unsigned)VOCAB;

    float bs = NEG_INF; unsigned bi = 0xFFFFFFFFu;
    float sk = 0.0f;

    for (int i = threadIdx.x; i < V4; i += blockDim.x){
        float4 f = x4[i];
        unsigned v0 = 4u * (unsigned)i;
        float vals[4] = {f.x, f.y, f.z, f.w};
        unsigned kx[4];
#pragma unroll
        for (int j = 0; j < 4; j++) kx[j] = okey(vals[j]);
        if (kx[0] < kEq && kx[1] < kEq && kx[2] < kEq && kx[3] < kEq) continue;
#pragma unroll
        for (int j = 0; j < 4; j++){
            unsigned v = v0 + j;
            if (kx[j] >= kGt || (kx[j] >= kEq && v >= loC)){
                float s = __fdiv_rn(vals[j], ts);
                sk += __expf(s - Ms);
                float sc = s + gumbel_from_bits(jax_bits32(iBase + v));
                if (sc > bs || (sc == bs && v < bi)){ bs = sc; bi = v; }
            }
        }
    }

    __shared__ float fv[1024];
    __shared__ unsigned iv[1024];
    __shared__ float dv[1024];
    fv[threadIdx.x] = bs; iv[threadIdx.x] = bi; dv[threadIdx.x] = sk;
    __syncthreads();
    for (int s = blockDim.x >> 1; s > 0; s >>= 1){
        if (threadIdx.x < s){
            float ov = fv[threadIdx.x + s]; unsigned oi = iv[threadIdx.x + s];
            if (ov > fv[threadIdx.x] ||
                (ov == fv[threadIdx.x] && oi < iv[threadIdx.x])){
                fv[threadIdx.x] = ov; iv[threadIdx.x] = oi;
            }
            dv[threadIdx.x] += dv[threadIdx.x + s];
        }
        __syncthreads();
    }

    if (threadIdx.x == 0){
        unsigned greedy = ~(unsigned)g_rowmax[row];
        unsigned tok = (t == 0.0f) ? greedy : iv[0];
        if (tok == 0xFFFFFFFFu) tok = greedy;   // safety
        float stok = __fdiv_rn(x[tok], ts);
        unsigned long long pT =
            ((unsigned long long)okey(stok) << 32) | tok;
        float sel = (pT >= C) ? stok : NEG_INF;
        float lz = Ms + logf(dv[0]);
        out[row]         = (float)tok;
        out[BATCH + row] = sel - lz;
    }
}

// ---------------- launch -----------------------------------------------------
extern "C" void kernel_launch(void* const* d_in, const int* in_sizes, int n_in,
                              void* d_out, int out_size){
    const float* logits = (const float*)d_in[0];
    const float* temps  = (const float*)d_in[1];
    const float* topps  = (const float*)d_in[2];
    float* out = (float*)d_out;

    k0_init  <<<1, 256>>>();
    k1_max   <<<dim3(4, BATCH), 512>>>(logits);
    k2_hist  <<<BATCH, 1024>>>(logits, temps, topps);
    k3_cut   <<<BATCH, 1024>>>(logits, temps, topps);
    k4_sample<<<BATCH, 1024>>>(logits, temps, out);
}

// round 4
// speedup vs baseline: 1.4811x; 1.2293x over previous
#include <cuda_runtime.h>
#include <math.h>
#include <stdint.h>

#define BATCH 256
#define VOCAB 128000
#define NBINS 8192
#define CAP   4096
#define CHUNKS 4                    // k2a chunks per row
#define SCHUNK (VOCAB/CHUNKS)       // 32000
#define KCH    8                    // k3a/k4a chunks per row
#define KCHE   (VOCAB/KCH)          // 16000
#define NEG_INF __int_as_float(0xff800000)
typedef unsigned long long ull;

// ---------------- scratch (device globals; no allocations allowed) ----------
__device__ float  g_hist[CHUNKS*BATCH*NBINS];   // 32MB per-chunk histograms
__device__ ull    g_cand[BATCH*CAP];            // 8MB boundary-bin candidates
__device__ int    g_ccount[BATCH];
__device__ ull    g_rowmax[BATCH];              // (okey(x)<<32) | ~argmax
__device__ ull    g_best[BATCH];                // (okey(gumbel score)<<32) | ~v
__device__ float  g_sk[BATCH];                  // kept mass (Ms-anchored)
__device__ int    g_Bstar[BATCH];
__device__ double g_cumAbove[BATCH];
__device__ double g_Z[BATCH];
__device__ ull    g_cut[BATCH];                 // keep <=> (okey(s),v) >= cut

// monotone float<->uint key (total order)
__device__ __forceinline__ unsigned okey(float f){
    unsigned b = __float_as_uint(f);
    return b ^ ((b & 0x80000000u) ? 0xFFFFFFFFu : 0x80000000u);
}
__device__ __forceinline__ float key_to_float(unsigned k){
    unsigned b = (k & 0x80000000u) ? (k ^ 0x80000000u) : ~k;
    return __uint_as_float(b);
}

// jax threefry2x32-20, key = (0, 42)
__device__ __forceinline__ void threefry(unsigned c0, unsigned c1,
                                         unsigned &o0, unsigned &o1){
    const unsigned k0 = 0u, k1 = 42u;
    const unsigned k2 = 0x1BD11BDAu ^ k0 ^ k1;
    unsigned x0 = c0 + k0, x1 = c1 + k1;
#define TFR(r) { x0 += x1; x1 = ((x1 << r) | (x1 >> (32 - r))); x1 ^= x0; }
    TFR(13) TFR(15) TFR(26) TFR(6)   x0 += k1; x1 += k2 + 1u;
    TFR(17) TFR(29) TFR(16) TFR(24)  x0 += k2; x1 += k0 + 2u;
    TFR(13) TFR(15) TFR(26) TFR(6)   x0 += k0; x1 += k1 + 3u;
    TFR(17) TFR(29) TFR(16) TFR(24)  x0 += k1; x1 += k2 + 4u;
    TFR(13) TFR(15) TFR(26) TFR(6)   x0 += k2; x1 += k0 + 5u;
#undef TFR
    o0 = x0; o1 = x1;
}
__device__ __forceinline__ unsigned jax_bits32(unsigned i){
    unsigned o0, o1; threefry(0u, i, o0, o1); return o0 ^ o1;
}
__device__ __forceinline__ float gumbel_from_bits(unsigned bits){
    float u = __uint_as_float((bits >> 9) | 0x3f800000u) - 1.0f;
    if (u <= 0.0f) u = 1.17549435e-38f;
    float inner = -log1pf(u - 1.0f);   // == -log(u) exactly
    return -logf(inner);
}

// minimal raw key kx with okey(rn(x/ts)) >= target (exact-div binary search)
__device__ unsigned lower_bound_key(float ts, unsigned target){
    unsigned lo = 0x00800000u, hi = 0xFF800000u;
    while (lo < hi){
        unsigned mid = lo + ((hi - lo) >> 1);
        float x = key_to_float(mid);
        unsigned sk = okey(__fdiv_rn(x, ts));
        if (sk >= target) hi = mid; else lo = mid + 1;
    }
    return lo;
}

// ---------------- K0: init ---------------------------------------------------
__global__ void k0_init(){
    int i = threadIdx.x;
    if (i < BATCH){
        g_rowmax[i] = 0ULL; g_best[i] = 0ULL;
        g_sk[i] = 0.0f;     g_ccount[i] = 0;
    }
}

// ---------------- K2a: raw-key histogram + row max (no division) -------------
__global__ void k2a_hist(const float* __restrict__ logits,
                         const float* __restrict__ temps){
    int row = blockIdx.y, part = blockIdx.x;
    __shared__ float bins[NBINS];
    __shared__ ull sp[512];
    for (int i = threadIdx.x; i < NBINS; i += 512) bins[i] = 0.0f;
    __syncthreads();

    float t = temps[row]; float ts = (t == 0.0f) ? 1.0f : t;
    float inv = 1.0f / ts;
    const float4* x4 =
        (const float4*)(logits + (size_t)row * VOCAB + part * SCHUNK);
    ull best = 0ULL;
    for (int i = threadIdx.x; i < SCHUNK/4; i += 512){
        float4 f = x4[i];
        unsigned v0 = (unsigned)(part * SCHUNK + 4 * i);
        float vals[4] = {f.x, f.y, f.z, f.w};
#pragma unroll
        for (int j = 0; j < 4; j++){
            unsigned kx = okey(vals[j]);
            ull p = ((ull)kx << 32) | (unsigned)(~(v0 + j));
            if (p > best) best = p;
            unsigned bin = kx >> 19;
            float xref = key_to_float((bin << 19) | 0x7FFFFu); // bin top edge
            atomicAdd(&bins[bin], __expf((vals[j] - xref) * inv));
        }
    }
    sp[threadIdx.x] = best; __syncthreads();
    for (int s = 256; s > 0; s >>= 1){
        if (threadIdx.x < s && sp[threadIdx.x + s] > sp[threadIdx.x])
            sp[threadIdx.x] = sp[threadIdx.x + s];
        __syncthreads();
    }
    if (threadIdx.x == 0) atomicMax(&g_rowmax[row], sp[0]);
    float* gh = g_hist + ((size_t)row * CHUNKS + part) * NBINS;
    for (int i = threadIdx.x; i < NBINS; i += 512) gh[i] = bins[i];
}

// ---------------- K2b: merge + rescale + suffix scan -> boundary bin ---------
__global__ void k2b_scan(const float* __restrict__ temps,
                         const float* __restrict__ topps){
    int row = blockIdx.x; int tid = threadIdx.x;   // 1024 threads
    __shared__ double sarr[1024];
    __shared__ int    sbi[1024];
    __shared__ double sZ;

    float t = temps[row]; float ts = (t == 0.0f) ? 1.0f : t;
    ull rm = g_rowmax[row];
    float xmax = key_to_float((unsigned)(rm >> 32));
    double invd = 1.0 / (double)ts;

    int base = tid * 8;
    double mv[8]; double csum = 0.0;
#pragma unroll
    for (int j = 0; j < 8; j++){
        int b = base + j;
        float S = 0.0f;
#pragma unroll
        for (int c = 0; c < CHUNKS; c++)
            S += g_hist[((size_t)row * CHUNKS + c) * NBINS + b];
        double m = 0.0;
        if (S > 0.0f){
            float xref = key_to_float(((unsigned)b << 19) | 0x7FFFFu);
            m = (double)S * exp(((double)xref - (double)xmax) * invd);
        }
        mv[j] = m; csum += m;
    }
    sarr[tid] = csum; __syncthreads();
    for (int off = 1; off < 1024; off <<= 1){
        double v = sarr[tid];
        double a = (tid + off < 1024) ? sarr[tid + off] : 0.0;
        __syncthreads();
        sarr[tid] = v + a;
        __syncthreads();
    }
    double above = sarr[tid] - csum;
    if (tid == 0) sZ = sarr[0];
    __syncthreads();
    double Z = sZ;

    float p = fminf(fmaxf(topps[row], 0.0f), 1.0f);
    double pZ = (double)p * Z;

    int bestj = -1; double bestAbove = 0.0;
    double run = above;
    for (int j = 7; j >= 0; j--){
        double s = mv[j];
        if (run + s > pZ){ bestj = base + j; bestAbove = run; break; }
        run += s;
    }
    __syncthreads();
    sbi[tid] = bestj; sarr[tid] = bestAbove; __syncthreads();
    for (int s2 = 512; s2 > 0; s2 >>= 1){
        if (tid < s2 && sbi[tid + s2] > sbi[tid]){
            sbi[tid] = sbi[tid + s2];
            sarr[tid] = sarr[tid + s2];
        }
        __syncthreads();
    }
    if (tid == 0){
        int B = sbi[0];
        if (Z <= 0.0 || B < 0){
            // degenerate (extreme temperature): keep only the max element
            float sMax = __fdiv_rn(xmax, ts);
            unsigned vmax = ~(unsigned)(rm & 0xFFFFFFFFu);
            g_Bstar[row] = -1;
            g_cut[row] = ((ull)okey(sMax) << 32) | vmax;
        } else {
            g_Bstar[row] = B;
            g_cumAbove[row] = sarr[0];
            g_Z[row] = Z;
        }
    }
}

// ---------------- K3a: gather boundary-bin candidates (pure int filter) ------
__global__ void k3a_gather(const float* __restrict__ logits,
                           const float* __restrict__ temps){
    int row = blockIdx.y;
    int Bstar = g_Bstar[row];
    if (Bstar < 0) return;
    float t = temps[row]; float ts = (t == 0.0f) ? 1.0f : t;
    int base = blockIdx.x * KCHE;
    const float4* x4 = (const float4*)(logits + (size_t)row * VOCAB + base);
    for (int i = threadIdx.x; i < KCHE/4; i += 256){
        float4 f = x4[i];
        unsigned v0 = (unsigned)(base + 4 * i);
        float vals[4] = {f.x, f.y, f.z, f.w};
#pragma unroll
        for (int j = 0; j < 4; j++){
            unsigned kx = okey(vals[j]);
            if ((int)(kx >> 19) == Bstar){
                float s = __fdiv_rn(vals[j], ts);
                int pos = atomicAdd(&g_ccount[row], 1);
                if (pos < CAP)
                    g_cand[(size_t)row * CAP + pos] =
                        ((ull)okey(s) << 32) | (v0 + j);
            }
        }
    }
}

// ---------------- K3b: sort candidates + exact cutoff ------------------------
__global__ void k3b_cut(const float* __restrict__ temps,
                        const float* __restrict__ topps){
    int row = blockIdx.x;
    int Bstar = g_Bstar[row];
    if (Bstar < 0) return;                    // cut already set by k2b
    __shared__ ull keys[CAP];                 // 32KB
    __shared__ double sarr[1024];
    __shared__ int sli[1024];

    float t = temps[row]; float ts = (t == 0.0f) ? 1.0f : t;
    double Ms = (double)__fdiv_rn(key_to_float((unsigned)(g_rowmax[row] >> 32)), ts);
    int count = min(g_ccount[row], CAP);
    if (count == 0){                          // guard; ~never
        if (threadIdx.x == 0){
            float xLo = key_to_float((unsigned)Bstar << 19);
            g_cut[row] = ((ull)okey(__fdiv_rn(xLo, ts)) << 32);
        }
        return;
    }
    int n = 1; while (n < count) n <<= 1; if (n < 2) n = 2;
    for (int i = threadIdx.x; i < n; i += blockDim.x)
        keys[i] = (i < count) ? g_cand[(size_t)row * CAP + i] : 0ULL;
    __syncthreads();

    // bitonic sort DESCENDING on packed (okey(s), idx)
    for (int k2 = 2; k2 <= n; k2 <<= 1){
        for (int j = k2 >> 1; j > 0; j >>= 1){
            for (int i = threadIdx.x; i < n; i += blockDim.x){
                int ixj = i ^ j;
                if (ixj > i){
                    ull a = keys[i], b = keys[ixj];
                    bool seg = ((i & k2) == 0);
                    if (seg ? (a < b) : (a > b)){ keys[i] = b; keys[ixj] = a; }
                }
            }
            __syncthreads();
        }
    }

    double pZ = (double)fminf(fmaxf(topps[row], 0.0f), 1.0f) * g_Z[row];
    double cumAbove = g_cumAbove[row];
    int m = (n + blockDim.x - 1) / blockDim.x;   // <= 4
    int lo = threadIdx.x * m;
    double ev[4];
    double ls = 0.0;
    for (int q = 0; q < m; q++){
        int i = lo + q; double e = 0.0;
        if (i < count){
            double sv = (double)key_to_float((unsigned)(keys[i] >> 32));
            e = exp(sv - Ms);
        }
        ev[q] = e; ls += e;
    }
    sarr[threadIdx.x] = ls; __syncthreads();
    for (int off = 1; off < 1024; off <<= 1){
        double v = sarr[threadIdx.x];
        double a = (threadIdx.x >= off) ? sarr[threadIdx.x - off] : 0.0;
        __syncthreads();
        sarr[threadIdx.x] = v + a;
        __syncthreads();
    }
    double run = sarr[threadIdx.x] - ls + cumAbove;
    int lastKept = -1;
    for (int q = 0; q < m; q++){
        int i = lo + q;
        run += ev[q];
        if (i < count && run <= pZ) lastKept = i;
    }
    sli[threadIdx.x] = lastKept; __syncthreads();
    for (int s2 = 512; s2 > 0; s2 >>= 1){
        if (threadIdx.x < s2)
            sli[threadIdx.x] = max(sli[threadIdx.x], sli[threadIdx.x + s2]);
        __syncthreads();
    }
    if (threadIdx.x == 0){
        int iL = sli[0];
        ull C;
        if (iL >= 0)                  C = keys[iL];
        else if (cumAbove > 0.0){
            // cut just above this bin: first s-key of next raw bin
            float xHi = key_to_float((unsigned)(Bstar + 1) << 19);
            C = ((ull)okey(__fdiv_rn(xHi, ts)) << 32);
        } else                        C = keys[0];  // force-keep top element
        g_cut[row] = C;
    }
}

// ---------------- K4a: gumbel-max sampling (chunked, raw-key fast filter) ----
__global__ void k4a_sample(const float* __restrict__ logits,
                           const float* __restrict__ temps){
    int row = blockIdx.y;
    int base = blockIdx.x * KCHE;
    const float4* x4 = (const float4*)(logits + (size_t)row * VOCAB + base);
    float t = temps[row]; float ts = (t == 0.0f) ? 1.0f : t;

    __shared__ float sMs;
    __shared__ unsigned sKEq, sKGt;
    ull C = g_cut[row];
    unsigned hiC = (unsigned)(C >> 32);
    unsigned loC = (unsigned)C;
    if (threadIdx.x == 0){
        sMs = __fdiv_rn(key_to_float((unsigned)(g_rowmax[row] >> 32)), ts);
        sKEq = lower_bound_key(ts, hiC);
        sKGt = (hiC == 0xFFFFFFFFu) ? 0xFF800000u
                                    : lower_bound_key(ts, hiC + 1u);
    }
    __syncthreads();
    float Ms = sMs; unsigned kEq = sKEq, kGt = sKGt;
    unsigned iBase = (unsigned)row * (unsigned)VOCAB;

    float bs = NEG_INF; unsigned bi = 0xFFFFFFFFu;
    float sk = 0.0f;
    for (int i = threadIdx.x; i < KCHE/4; i += 256){
        float4 f = x4[i];
        unsigned v0 = (unsigned)(base + 4 * i);
        float vals[4] = {f.x, f.y, f.z, f.w};
        unsigned kx[4];
#pragma unroll
        for (int j = 0; j < 4; j++) kx[j] = okey(vals[j]);
        if (kx[0] < kEq && kx[1] < kEq && kx[2] < kEq && kx[3] < kEq) continue;
#pragma unroll
        for (int j = 0; j < 4; j++){
            unsigned v = v0 + j;
            if (kx[j] >= kGt || (kx[j] >= kEq && v >= loC)){
                float s = __fdiv_rn(vals[j], ts);
                sk += __expf(s - Ms);
                float sc = s + gumbel_from_bits(jax_bits32(iBase + v));
                if (sc > bs || (sc == bs && v < bi)){ bs = sc; bi = v; }
            }
        }
    }

    __shared__ ull sp[256];
    __shared__ float sv[256];
    sp[threadIdx.x] = ((ull)okey(bs) << 32) | (unsigned)(~bi);
    sv[threadIdx.x] = sk;
    __syncthreads();
    for (int s = 128; s > 0; s >>= 1){
        if (threadIdx.x < s){
            if (sp[threadIdx.x + s] > sp[threadIdx.x])
                sp[threadIdx.x] = sp[threadIdx.x + s];
            sv[threadIdx.x] += sv[threadIdx.x + s];
        }
        __syncthreads();
    }
    if (threadIdx.x == 0){
        if (bi != 0xFFFFFFFFu || sp[0] != (((ull)okey(NEG_INF) << 32) | 0xFFFFFFFFu) ){
            // merge partials (contributes even if this chunk had no kept elems:
            // packed NEG_INF/-1 loses every atomicMax against a real candidate)
        }
        atomicMax(&g_best[row], sp[0]);
        if (sv[0] != 0.0f) atomicAdd(&g_sk[row], sv[0]);
    }
}

// ---------------- K4b: finalize ----------------------------------------------
__global__ void k4b_final(const float* __restrict__ logits,
                          const float* __restrict__ temps,
                          float* __restrict__ out){
    int row = threadIdx.x;   // 256 threads, 1 block
    if (row >= BATCH) return;
    float t = temps[row]; float ts = (t == 0.0f) ? 1.0f : t;
    ull rm = g_rowmax[row];
    float Ms = __fdiv_rn(key_to_float((unsigned)(rm >> 32)), ts);
    unsigned greedy = ~(unsigned)(rm & 0xFFFFFFFFu);
    ull C = g_cut[row];
    unsigned tok;
    if (t == 0.0f) tok = greedy;
    else {
        ull b = g_best[row];
        unsigned cand = ~(unsigned)(b & 0xFFFFFFFFu);
        tok = (cand < (unsigned)VOCAB) ? cand : greedy;
    }
    float stok = __fdiv_rn(logits[(size_t)row * VOCAB + tok], ts);
    ull pT = ((ull)okey(stok) << 32) | tok;
    float sel = (pT >= C) ? stok : NEG_INF;
    float lz = Ms + logf(g_sk[row]);
    out[row]          = (float)tok;
    out[BATCH + row]  = sel - lz;
}

// ---------------- launch -----------------------------------------------------
extern "C" void kernel_launch(void* const* d_in, const int* in_sizes, int n_in,
                              void* d_out, int out_size){
    const float* logits = (const float*)d_in[0];
    const float* temps  = (const float*)d_in[1];
    const float* topps  = (const float*)d_in[2];
    float* out = (float*)d_out;

    k0_init   <<<1, 256>>>();
    k2a_hist  <<<dim3(CHUNKS, BATCH), 512>>>(logits, temps);
    k2b_scan  <<<BATCH, 1024>>>(temps, topps);
    k3a_gather<<<dim3(KCH, BATCH), 256>>>(logits, temps);
    k3b_cut   <<<BATCH, 1024>>>(temps, topps);
    k4a_sample<<<dim3(KCH, BATCH), 256>>>(logits, temps);
    k4b_final <<<1, 256>>>(logits, temps, out);
}